// round 1
// baseline (speedup 1.0000x reference)
#include <cuda_runtime.h>
#include <stdint.h>

#define D     10000
#define NB    64
#define NS    128
#define NA    10
#define NR    8
#define NP    256
#define FFTTHREADS 512
#define BG    8          // batches per combine block
#define DSPLIT 16
#define DLEN  625        // D / DSPLIT
#define TD    25

#define PI_D 3.14159265358979323846

// ---------------- device scratch (static, no allocations) ----------------
__device__ float2 Wtab_g[D];          // exp(-2*pi*i*k/D)
__device__ float2 Fa_g[NA * D];
__device__ float2 Fp_g[NS * D];
__device__ float2 Fc_g[D];
__device__ float2 Freq_g[NB * D];
__device__ float  Mol_g[NB * D];

__device__ __forceinline__ float2 cmulf(float2 a, float2 b) {
    return make_float2(a.x * b.x - a.y * b.y, a.x * b.y + a.y * b.x);
}

// ---------------- twiddle table (fp64 accuracy) ----------------
__global__ void build_twiddle_kernel() {
    int k = blockIdx.x * blockDim.x + threadIdx.x;
    if (k < D) {
        double ang = -2.0 * PI_D * (double)k / (double)D;
        Wtab_g[k] = make_float2((float)cos(ang), (float)sin(ang));
    }
}

// ---------------- radix-10 Stockham FFT core (N = 10000, 4 stages) ------
// bufA holds input; result ends back in bufA. Both are SMEM, D float2 each.
__device__ void fft_core(float2* bufA, float2* bufB) {
    // DFT-10 twiddles in registers (compile-time indexed)
    float2 w10[10];
#pragma unroll
    for (int k = 0; k < 10; k++) w10[k] = Wtab_g[k * (D / 10)];

    float2* src = bufA;
    float2* dst = bufB;
    int l = 1000, m = 1, step = 1;
#pragma unroll
    for (int stage = 0; stage < 4; stage++) {
        for (int bf = threadIdx.x; bf < 1000; bf += blockDim.x) {
            int j = bf / m;
            int k = bf - j * m;
            float2 u[10];
#pragma unroll
            for (int q = 0; q < 10; q++) u[q] = src[k + (j + q * l) * m];
            float2 v[10];
#pragma unroll
            for (int t = 0; t < 10; t++) {
                float vr = 0.f, vi = 0.f;
#pragma unroll
                for (int q = 0; q < 10; q++) {
                    float2 w = w10[(q * t) % 10];   // constant index after unroll
                    vr += u[q].x * w.x - u[q].y * w.y;
                    vi += u[q].x * w.y + u[q].y * w.x;
                }
                v[t] = make_float2(vr, vi);
            }
            // stage twiddle: exp(-2*pi*i * j*t / (r*l)) = Wtab[j*t*step]
#pragma unroll
            for (int t = 1; t < 10; t++) {
                float2 w = Wtab_g[j * t * step];
                v[t] = cmulf(v[t], w);
            }
#pragma unroll
            for (int t = 0; t < 10; t++) dst[k + (10 * j + t) * m] = v[t];
        }
        __syncthreads();
        float2* tmp = src; src = dst; dst = tmp;
        l /= 10; m *= 10; step *= 10;
    }
    // 4 swaps: result is back in bufA, and we are synced.
}

// ---------------- forward FFT of atom/pos/closure ----------------
__global__ void __launch_bounds__(FFTTHREADS)
fwd_fft_kernel(const float* __restrict__ atom,
               const float* __restrict__ pos,
               const float* __restrict__ clos) {
    extern __shared__ float2 sb[];
    int v = blockIdx.x;  // 0..138
    const float* x;
    float2* out;
    if (v < NA)            { x = atom + v * D;        out = Fa_g + v * D; }
    else if (v < NA + NS)  { x = pos + (v - NA) * D;  out = Fp_g + (v - NA) * D; }
    else                   { x = clos;                out = Fc_g; }

    for (int i = threadIdx.x; i < D; i += blockDim.x)
        sb[i] = make_float2(x[i], 0.f);
    __syncthreads();
    fft_core(sb, sb + D);
    for (int i = threadIdx.x; i < D; i += blockDim.x)
        out[i] = sb[i];
}

// ---------------- frequency-domain bind + bundle (tokens + rings) -------
__global__ void combine_kernel(const float* __restrict__ tmask,
                               const float* __restrict__ rmask,
                               const int*   __restrict__ aidx,
                               const int*   __restrict__ rpos) {
    __shared__ int   s_idx[BG][NS];
    __shared__ float s_m[BG][NS];
    __shared__ int   s_rp[BG][NR][2];
    __shared__ float s_rm[BG][NR];
    __shared__ float2 s_fa[NA][128];   // Fa for this f-tile, 10 KB

    int b0 = blockIdx.y * BG;
    int tx = threadIdx.x;              // 128 threads

    for (int t = tx; t < BG * NS; t += 128) {
        int bb = t / NS, s = t % NS;
        s_idx[bb][s] = aidx[(b0 + bb) * NS + s];
        s_m[bb][s]   = tmask[(b0 + bb) * NS + s];
    }
    for (int t = tx; t < BG * NR; t += 128) {
        int bb = t / NR, r = t % NR;
        s_rp[bb][r][0] = rpos[((b0 + bb) * NR + r) * 2 + 0];
        s_rp[bb][r][1] = rpos[((b0 + bb) * NR + r) * 2 + 1];
        s_rm[bb][r]    = rmask[(b0 + bb) * NR + r];
    }
    int f = blockIdx.x * 128 + tx;
    if (f < D) {
        for (int i = 0; i < NA; i++) s_fa[i][tx] = Fa_g[i * D + f];
    }
    __syncthreads();
    if (f >= D) return;

    float2 fc = Fc_g[f];
    float2 acc[BG];
#pragma unroll
    for (int bb = 0; bb < BG; bb++) acc[bb] = make_float2(0.f, 0.f);

    // token bind+bundle: sum_s mask * Fa[idx] * Fp[s]
    for (int s = 0; s < NS; s++) {
        float2 fp = Fp_g[s * D + f];
#pragma unroll
        for (int bb = 0; bb < BG; bb++) {
            int   a  = s_idx[bb][s];
            float mm = s_m[bb][s];
            float2 fa = s_fa[a][tx];
            acc[bb].x += mm * (fa.x * fp.x - fa.y * fp.y);
            acc[bb].y += mm * (fa.x * fp.y + fa.y * fp.x);
        }
    }
    // rings: sum_r rmask * Fp[p0]*Fp[p1]*Fc
#pragma unroll
    for (int bb = 0; bb < BG; bb++) {
        for (int r = 0; r < NR; r++) {
            float2 f0 = Fp_g[s_rp[bb][r][0] * D + f];
            float2 f1 = Fp_g[s_rp[bb][r][1] * D + f];
            float2 t  = cmulf(cmulf(f0, f1), fc);
            float mm  = s_rm[bb][r];
            acc[bb].x += mm * t.x;
            acc[bb].y += mm * t.y;
        }
    }
#pragma unroll
    for (int bb = 0; bb < BG; bb++)
        Freq_g[(b0 + bb) * D + f] = acc[bb];
}

// ---------------- inverse FFT: ifft(X) = conj(fft(conj(X)))/N; keep Re --
__global__ void __launch_bounds__(FFTTHREADS)
inv_fft_kernel() {
    extern __shared__ float2 sb[];
    int b = blockIdx.x;
    const float2* in = Freq_g + b * D;
    for (int i = threadIdx.x; i < D; i += blockDim.x) {
        float2 z = in[i];
        sb[i] = make_float2(z.x, -z.y);
    }
    __syncthreads();
    fft_core(sb, sb + D);
    const float inv = 1.0f / (float)D;
    for (int i = threadIdx.x; i < D; i += blockDim.x)
        Mol_g[b * D + i] = sb[i].x * inv;
}

// ---------------- projection: out = Mol @ W^T + bias ----------------
__global__ void init_out_kernel(const float* __restrict__ bias,
                                float* __restrict__ out) {
    int b = blockIdx.x, p = threadIdx.x;
    out[b * NP + p] = bias[p];
}

__global__ void proj_kernel(const float* __restrict__ Wm,
                            float* __restrict__ out) {
    // grid: (NP/32 = 8, DSPLIT = 16); block 256 = 32 p-lanes x 8 b-groups
    __shared__ float sA[64][TD];       // Mol tile [b][dd]
    __shared__ float sW[32][TD + 2];   // pad to 27 -> conflict-free
    int pb = blockIdx.x;
    int ds = blockIdx.y;
    int tx = threadIdx.x % 32;         // p within tile
    int ty = threadIdx.x / 32;         // b group
    float acc[8];
#pragma unroll
    for (int i = 0; i < 8; i++) acc[i] = 0.f;
    int dbase = ds * DLEN;
    for (int dt = 0; dt < DLEN; dt += TD) {
        for (int t = threadIdx.x; t < 64 * TD; t += 256) {
            int bb = t / TD, dd = t % TD;
            sA[bb][dd] = Mol_g[bb * D + dbase + dt + dd];
        }
        for (int t = threadIdx.x; t < 32 * TD; t += 256) {
            int pp = t / TD, dd = t % TD;
            sW[pp][dd] = Wm[(pb * 32 + pp) * D + dbase + dt + dd];
        }
        __syncthreads();
#pragma unroll
        for (int dd = 0; dd < TD; dd++) {
            float wv = sW[tx][dd];
#pragma unroll
            for (int bb = 0; bb < 8; bb++)
                acc[bb] += sA[ty * 8 + bb][dd] * wv;
        }
        __syncthreads();
    }
    int p = pb * 32 + tx;
#pragma unroll
    for (int bb = 0; bb < 8; bb++)
        atomicAdd(&out[(ty * 8 + bb) * NP + p], acc[bb]);
}

// ---------------- launch ----------------
extern "C" void kernel_launch(void* const* d_in, const int* in_sizes, int n_in,
                              void* d_out, int out_size) {
    const float* atom  = (const float*)d_in[0];   // [10, 10000]
    const float* pos   = (const float*)d_in[1];   // [128, 10000]
    const float* clos  = (const float*)d_in[2];   // [10000]
    const float* Wm    = (const float*)d_in[3];   // [256, 10000]
    const float* bias  = (const float*)d_in[4];   // [256]
    const float* tmask = (const float*)d_in[5];   // [64, 128]
    const float* rmask = (const float*)d_in[6];   // [64, 8]
    const int*   aidx  = (const int*)d_in[7];     // [64, 128]
    const int*   rpos  = (const int*)d_in[8];     // [64, 8, 2]
    float* out = (float*)d_out;                   // [64, 256]

    size_t smem = 2 * (size_t)D * sizeof(float2); // 160000 B ping-pong
    cudaFuncSetAttribute(fwd_fft_kernel,
                         cudaFuncAttributeMaxDynamicSharedMemorySize, (int)smem);
    cudaFuncSetAttribute(inv_fft_kernel,
                         cudaFuncAttributeMaxDynamicSharedMemorySize, (int)smem);

    build_twiddle_kernel<<<(D + 255) / 256, 256>>>();
    fwd_fft_kernel<<<NA + NS + 1, FFTTHREADS, smem>>>(atom, pos, clos);

    dim3 cg((D + 127) / 128, NB / BG);
    combine_kernel<<<cg, 128>>>(tmask, rmask, aidx, rpos);

    inv_fft_kernel<<<NB, FFTTHREADS, smem>>>();

    init_out_kernel<<<NB, NP>>>(bias, out);
    dim3 pg(NP / 32, DSPLIT);
    proj_kernel<<<pg, 256>>>(Wm, out);
}

// round 2
// speedup vs baseline: 1.2231x; 1.2231x over previous
#include <cuda_runtime.h>
#include <stdint.h>

#define D     10000
#define F     5001      // Hermitian bins 0..5000
#define NB    64
#define NS    128
#define NA    10
#define NR    8
#define NP    256
#define FFTTHREADS 1024
#define BG    8
#define DSPLIT 16
#define DLEN  625
#define TD    25

// skewed smem index: pad every 16 float2 (128B) to break store conflicts
#define SK(i) ((i) + ((i) >> 4))
#define SBUF  10624      // SK(9999)+1 = 10624

// ---------------- device scratch ----------------
__device__ float2 Wtab_g[D];
__device__ float2 Fa_g[NA * F];
__device__ float2 Fp_g[NS * F];
__device__ float2 Fc_g[F];
__device__ float2 Freq_g[NB * F];
__device__ float  Mol_g[NB * D];

__device__ __forceinline__ float2 cmulf(float2 a, float2 b) {
    return make_float2(a.x * b.x - a.y * b.y, a.x * b.y + a.y * b.x);
}

// ---------------- twiddles: fp32 sincospif (no fp64!) ----------------
__global__ void build_twiddle_kernel() {
    int k = blockIdx.x * blockDim.x + threadIdx.x;
    if (k < D) {
        float t = -(float)k / 5000.0f;     // angle / pi
        float s, c;
        sincospif(t, &s, &c);
        Wtab_g[k] = make_float2(c, s);
    }
}

// ---------------- radix-10 Stockham FFT core (N=10000, 4 stages) ------
// result ends back in bufA, synced.
__device__ void fft_core(float2* bufA, float2* bufB) {
    float2 w10[10];
#pragma unroll
    for (int k = 0; k < 10; k++) w10[k] = Wtab_g[k * 1000];

    float2* src = bufA;
    float2* dst = bufB;
    int m = 1, step = 1;
#pragma unroll
    for (int stage = 0; stage < 4; stage++) {
        for (int bf = threadIdx.x; bf < 1000; bf += blockDim.x) {
            int j = bf / m;
            int k = bf - j * m;
            float2 u[10];
#pragma unroll
            for (int q = 0; q < 10; q++) u[q] = src[SK(bf + q * 1000)];
            float2 v[10];
#pragma unroll
            for (int t = 0; t < 10; t++) {
                float vr = 0.f, vi = 0.f;
#pragma unroll
                for (int q = 0; q < 10; q++) {
                    float2 w = w10[(q * t) % 10];
                    vr += u[q].x * w.x - u[q].y * w.y;
                    vi += u[q].x * w.y + u[q].y * w.x;
                }
                v[t] = make_float2(vr, vi);
            }
            // stage twiddle W^(j*t*step) via chain (1 LDG instead of 9)
            if (j != 0) {
                float2 w1 = Wtab_g[j * step];
                float2 wc = w1;
                v[1] = cmulf(v[1], wc);
#pragma unroll
                for (int t = 2; t < 10; t++) {
                    wc = cmulf(wc, w1);
                    v[t] = cmulf(v[t], wc);
                }
            }
            int ob = k + 10 * j * m;
#pragma unroll
            for (int t = 0; t < 10; t++) dst[SK(ob + t * m)] = v[t];
        }
        __syncthreads();
        float2* tmp = src; src = dst; dst = tmp;
        m *= 10; step *= 10;
    }
}

// ---------------- forward FFT: store Hermitian half only ----------------
__global__ void __launch_bounds__(FFTTHREADS, 1)
fwd_fft_kernel(const float* __restrict__ atom,
               const float* __restrict__ pos,
               const float* __restrict__ clos) {
    extern __shared__ float2 sb[];
    int v = blockIdx.x;
    const float* x;
    float2* out;
    if (v < NA)            { x = atom + v * D;        out = Fa_g + v * F; }
    else if (v < NA + NS)  { x = pos + (v - NA) * D;  out = Fp_g + (v - NA) * F; }
    else                   { x = clos;                out = Fc_g; }

    for (int i = threadIdx.x; i < D; i += blockDim.x)
        sb[SK(i)] = make_float2(x[i], 0.f);
    __syncthreads();
    fft_core(sb, sb + SBUF);
    for (int i = threadIdx.x; i < F; i += blockDim.x)
        out[i] = sb[SK(i)];
}

// ---------------- frequency combine (bins 0..5000 only) ----------------
__global__ void combine_kernel(const float* __restrict__ tmask,
                               const float* __restrict__ rmask,
                               const int*   __restrict__ aidx,
                               const int*   __restrict__ rpos) {
    __shared__ int   s_idx[BG][NS];
    __shared__ float s_m[BG][NS];
    __shared__ int   s_rp[BG][NR][2];
    __shared__ float s_rm[BG][NR];
    __shared__ float2 s_fa[NA][128];

    int b0 = blockIdx.y * BG;
    int tx = threadIdx.x;

    for (int t = tx; t < BG * NS; t += 128) {
        int bb = t / NS, s = t % NS;
        s_idx[bb][s] = aidx[(b0 + bb) * NS + s];
        s_m[bb][s]   = tmask[(b0 + bb) * NS + s];
    }
    for (int t = tx; t < BG * NR; t += 128) {
        int bb = t / NR, r = t % NR;
        s_rp[bb][r][0] = rpos[((b0 + bb) * NR + r) * 2 + 0];
        s_rp[bb][r][1] = rpos[((b0 + bb) * NR + r) * 2 + 1];
        s_rm[bb][r]    = rmask[(b0 + bb) * NR + r];
    }
    int f = blockIdx.x * 128 + tx;
    if (f < F) {
        for (int i = 0; i < NA; i++) s_fa[i][tx] = Fa_g[i * F + f];
    }
    __syncthreads();
    if (f >= F) return;

    float2 fc = Fc_g[f];
    float2 acc[BG];
#pragma unroll
    for (int bb = 0; bb < BG; bb++) acc[bb] = make_float2(0.f, 0.f);

    for (int s = 0; s < NS; s++) {
        float2 fp = Fp_g[s * F + f];
#pragma unroll
        for (int bb = 0; bb < BG; bb++) {
            int   a  = s_idx[bb][s];
            float mm = s_m[bb][s];
            float2 fa = s_fa[a][tx];
            acc[bb].x += mm * (fa.x * fp.x - fa.y * fp.y);
            acc[bb].y += mm * (fa.x * fp.y + fa.y * fp.x);
        }
    }
#pragma unroll
    for (int bb = 0; bb < BG; bb++) {
        for (int r = 0; r < NR; r++) {
            float2 f0 = Fp_g[s_rp[bb][r][0] * F + f];
            float2 f1 = Fp_g[s_rp[bb][r][1] * F + f];
            float2 t  = cmulf(cmulf(f0, f1), fc);
            float mm  = s_rm[bb][r];
            acc[bb].x += mm * t.x;
            acc[bb].y += mm * t.y;
        }
    }
#pragma unroll
    for (int bb = 0; bb < BG; bb++)
        Freq_g[(b0 + bb) * F + f] = acc[bb];
}

// ---------------- inverse FFT (Hermitian reconstruct + conj trick) -----
__global__ void __launch_bounds__(FFTTHREADS, 1)
inv_fft_kernel() {
    extern __shared__ float2 sb[];
    int b = blockIdx.x;
    const float2* in = Freq_g + b * F;
    for (int i = threadIdx.x; i < D; i += blockDim.x) {
        float2 z;
        if (i < F) { z = in[i]; z.y = -z.y; }     // conj(X[i])
        else       { z = in[D - i]; }             // conj(conj(X[D-i])) = X[D-i]
        sb[SK(i)] = z;
    }
    __syncthreads();
    fft_core(sb, sb + SBUF);
    const float inv = 1.0f / (float)D;
    for (int i = threadIdx.x; i < D; i += blockDim.x)
        Mol_g[b * D + i] = sb[SK(i)].x * inv;
}

// ---------------- projection ----------------
__global__ void init_out_kernel(const float* __restrict__ bias,
                                float* __restrict__ out) {
    int b = blockIdx.x, p = threadIdx.x;
    out[b * NP + p] = bias[p];
}

__global__ void proj_kernel(const float* __restrict__ Wm,
                            float* __restrict__ out) {
    __shared__ float sA[64][TD];
    __shared__ float sW[32][TD + 2];
    int pb = blockIdx.x;
    int ds = blockIdx.y;
    int tx = threadIdx.x % 32;
    int ty = threadIdx.x / 32;
    float acc[8];
#pragma unroll
    for (int i = 0; i < 8; i++) acc[i] = 0.f;
    int dbase = ds * DLEN;
    for (int dt = 0; dt < DLEN; dt += TD) {
        for (int t = threadIdx.x; t < 64 * TD; t += 256) {
            int bb = t / TD, dd = t % TD;
            sA[bb][dd] = Mol_g[bb * D + dbase + dt + dd];
        }
        for (int t = threadIdx.x; t < 32 * TD; t += 256) {
            int pp = t / TD, dd = t % TD;
            sW[pp][dd] = Wm[(pb * 32 + pp) * D + dbase + dt + dd];
        }
        __syncthreads();
#pragma unroll
        for (int dd = 0; dd < TD; dd++) {
            float wv = sW[tx][dd];
#pragma unroll
            for (int bb = 0; bb < 8; bb++)
                acc[bb] += sA[ty * 8 + bb][dd] * wv;
        }
        __syncthreads();
    }
    int p = pb * 32 + tx;
#pragma unroll
    for (int bb = 0; bb < 8; bb++)
        atomicAdd(&out[(ty * 8 + bb) * NP + p], acc[bb]);
}

// ---------------- launch ----------------
extern "C" void kernel_launch(void* const* d_in, const int* in_sizes, int n_in,
                              void* d_out, int out_size) {
    const float* atom  = (const float*)d_in[0];
    const float* pos   = (const float*)d_in[1];
    const float* clos  = (const float*)d_in[2];
    const float* Wm    = (const float*)d_in[3];
    const float* bias  = (const float*)d_in[4];
    const float* tmask = (const float*)d_in[5];
    const float* rmask = (const float*)d_in[6];
    const int*   aidx  = (const int*)d_in[7];
    const int*   rpos  = (const int*)d_in[8];
    float* out = (float*)d_out;

    size_t smem = 2 * (size_t)SBUF * sizeof(float2);   // 169984 B
    cudaFuncSetAttribute(fwd_fft_kernel,
                         cudaFuncAttributeMaxDynamicSharedMemorySize, (int)smem);
    cudaFuncSetAttribute(inv_fft_kernel,
                         cudaFuncAttributeMaxDynamicSharedMemorySize, (int)smem);

    build_twiddle_kernel<<<(D + 255) / 256, 256>>>();
    fwd_fft_kernel<<<NA + NS + 1, FFTTHREADS, smem>>>(atom, pos, clos);

    dim3 cg((F + 127) / 128, NB / BG);
    combine_kernel<<<cg, 128>>>(tmask, rmask, aidx, rpos);

    inv_fft_kernel<<<NB, FFTTHREADS, smem>>>();

    init_out_kernel<<<NB, NP>>>(bias, out);
    dim3 pg(NP / 32, DSPLIT);
    proj_kernel<<<pg, 256>>>(Wm, out);
}

// round 3
// speedup vs baseline: 1.9032x; 1.5560x over previous
#include <cuda_runtime.h>
#include <stdint.h>

#define D     10000
#define F     5001      // Hermitian bins 0..5000
#define NB    64
#define NS    128
#define NA    10
#define NR    8
#define NP    256
#define FFTTHREADS 512
#define BG    8

// proj tiling
#define DSPLIT 125
#define DLEN   80       // D / DSPLIT

// skewed smem index: pad every 16 float2 (128B) to break conflicts
#define SK(i) ((i) + ((i) >> 4))
#define SBUF  10624      // SK(9999)+1

// ---------------- device scratch ----------------
__device__ float2 T_g[1000 * 10];     // T[j][t] = exp(-2*pi*i*j*t/D), j<1000, t<10
__device__ float2 Fa_g[NA * F];
__device__ float2 Fp_g[NS * F];
__device__ float2 Fc_g[F];
__device__ float2 Freq_g[NB * F];
__device__ float  Mol_g[NB * D];

__device__ __forceinline__ float2 cmulf(float2 a, float2 b) {
    return make_float2(a.x * b.x - a.y * b.y, a.x * b.y + a.y * b.x);
}

// DFT-5 constants: W5 = e^{-2pi i/5}
#define C51  0.30901699437494742f
#define S51  0.95105651629515357f
#define C52 (-0.80901699437494745f)
#define S52  0.58778525229247314f
// W10^t = (CT_t, -ST_t)
#define CT1  0.80901699437494742f
#define ST1  0.58778525229247314f
#define CT2  0.30901699437494742f
#define ST2  0.95105651629515357f

// ---------------- twiddle table build ----------------
__global__ void build_T_kernel() {
    int i = blockIdx.x * blockDim.x + threadIdx.x;
    if (i < 10000) {
        int j = i / 10, t = i % 10;
        float s, c;
        sincospif(-(float)(j * t) / 5000.0f, &s, &c);
        T_g[i] = make_float2(c, s);
    }
}

// ---------------- DFT-5 (Winograd-style, immediate constants) ----------
__device__ __forceinline__ void dft5(const float2* a, float2* A) {
    float2 t1 = make_float2(a[1].x + a[4].x, a[1].y + a[4].y);
    float2 t2 = make_float2(a[2].x + a[3].x, a[2].y + a[3].y);
    float2 t3 = make_float2(a[1].x - a[4].x, a[1].y - a[4].y);
    float2 t4 = make_float2(a[2].x - a[3].x, a[2].y - a[3].y);
    A[0] = make_float2(a[0].x + t1.x + t2.x, a[0].y + t1.y + t2.y);
    float2 b1 = make_float2(a[0].x + C51 * t1.x + C52 * t2.x,
                            a[0].y + C51 * t1.y + C52 * t2.y);
    float2 b2 = make_float2(a[0].x + C52 * t1.x + C51 * t2.x,
                            a[0].y + C52 * t1.y + C51 * t2.y);
    float2 p  = make_float2(S51 * t3.x + S52 * t4.x, S51 * t3.y + S52 * t4.y);
    float2 q  = make_float2(S52 * t3.x - S51 * t4.x, S52 * t3.y - S51 * t4.y);
    A[1] = make_float2(b1.x + p.y, b1.y - p.x);
    A[4] = make_float2(b1.x - p.y, b1.y + p.x);
    A[2] = make_float2(b2.x + q.y, b2.y - q.x);
    A[3] = make_float2(b2.x - q.y, b2.y + q.x);
}

// ---------------- radix-10 Stockham core (N=10000, 4 stages) -----------
// result ends back in bufA, synced.
__device__ void fft_core(float2* bufA, float2* bufB) {
    float2* src = bufA;
    float2* dst = bufB;
    int m = 1, step = 1;
#pragma unroll
    for (int stage = 0; stage < 4; stage++) {
        for (int bf = threadIdx.x; bf < 1000; bf += blockDim.x) {
            int j = bf / m;
            int k = bf - j * m;
            float2 u[10];
#pragma unroll
            for (int q = 0; q < 10; q++) u[q] = src[SK(bf + q * 1000)];

            // DFT-10 = 2 x DFT-5 + radix-2 combine (all constants immediate)
            float2 E[5], O[5];
            {
                float2 a[5];
#pragma unroll
                for (int r = 0; r < 5; r++) a[r] = u[2 * r];
                dft5(a, E);
#pragma unroll
                for (int r = 0; r < 5; r++) a[r] = u[2 * r + 1];
                dft5(a, O);
            }
            float2 v[10];
            {
                float2 wo;
                // t=0
                v[0] = make_float2(E[0].x + O[0].x, E[0].y + O[0].y);
                v[5] = make_float2(E[0].x - O[0].x, E[0].y - O[0].y);
                // t=1: W10^1 = (CT1, -ST1)
                wo = cmulf(O[1], make_float2(CT1, -ST1));
                v[1] = make_float2(E[1].x + wo.x, E[1].y + wo.y);
                v[6] = make_float2(E[1].x - wo.x, E[1].y - wo.y);
                // t=2
                wo = cmulf(O[2], make_float2(CT2, -ST2));
                v[2] = make_float2(E[2].x + wo.x, E[2].y + wo.y);
                v[7] = make_float2(E[2].x - wo.x, E[2].y - wo.y);
                // t=3
                wo = cmulf(O[3], make_float2(-CT2, -ST2));
                v[3] = make_float2(E[3].x + wo.x, E[3].y + wo.y);
                v[8] = make_float2(E[3].x - wo.x, E[3].y - wo.y);
                // t=4
                wo = cmulf(O[4], make_float2(-CT1, -ST1));
                v[4] = make_float2(E[4].x + wo.x, E[4].y + wo.y);
                v[9] = make_float2(E[4].x - wo.x, E[4].y - wo.y);
            }

            // stage twiddle from table row j*step (coalesced 16B loads)
            if (j != 0) {
                const float4* tp =
                    reinterpret_cast<const float4*>(T_g + (j * step) * 10);
                float4 r0 = tp[0], r1 = tp[1], r2 = tp[2], r3 = tp[3], r4 = tp[4];
                v[1] = cmulf(v[1], make_float2(r0.z, r0.w));
                v[2] = cmulf(v[2], make_float2(r1.x, r1.y));
                v[3] = cmulf(v[3], make_float2(r1.z, r1.w));
                v[4] = cmulf(v[4], make_float2(r2.x, r2.y));
                v[5] = cmulf(v[5], make_float2(r2.z, r2.w));
                v[6] = cmulf(v[6], make_float2(r3.x, r3.y));
                v[7] = cmulf(v[7], make_float2(r3.z, r3.w));
                v[8] = cmulf(v[8], make_float2(r4.x, r4.y));
                v[9] = cmulf(v[9], make_float2(r4.z, r4.w));
            }
            int ob = k + 10 * j * m;
#pragma unroll
            for (int t = 0; t < 10; t++) dst[SK(ob + t * m)] = v[t];
        }
        __syncthreads();
        float2* tmp = src; src = dst; dst = tmp;
        m *= 10; step *= 10;
    }
}

// ---------------- forward FFT (store Hermitian half) ----------------
__global__ void __launch_bounds__(FFTTHREADS)
fwd_fft_kernel(const float* __restrict__ atom,
               const float* __restrict__ pos,
               const float* __restrict__ clos) {
    extern __shared__ float2 sb[];
    int v = blockIdx.x;
    const float* x;
    float2* out;
    if (v < NA)            { x = atom + v * D;        out = Fa_g + v * F; }
    else if (v < NA + NS)  { x = pos + (v - NA) * D;  out = Fp_g + (v - NA) * F; }
    else                   { x = clos;                out = Fc_g; }

    for (int i = threadIdx.x; i < D; i += blockDim.x)
        sb[SK(i)] = make_float2(x[i], 0.f);
    __syncthreads();
    fft_core(sb, sb + SBUF);
    for (int i = threadIdx.x; i < F; i += blockDim.x)
        out[i] = sb[SK(i)];
}

// ---------------- frequency combine (bins 0..5000) ----------------
__global__ void combine_kernel(const float* __restrict__ tmask,
                               const float* __restrict__ rmask,
                               const int*   __restrict__ aidx,
                               const int*   __restrict__ rpos) {
    __shared__ int   s_idx[BG][NS];
    __shared__ float s_m[BG][NS];
    __shared__ int   s_rp[BG][NR][2];
    __shared__ float s_rm[BG][NR];
    __shared__ float2 s_fa[NA][128];

    int b0 = blockIdx.y * BG;
    int tx = threadIdx.x;

    for (int t = tx; t < BG * NS; t += 128) {
        int bb = t / NS, s = t % NS;
        s_idx[bb][s] = aidx[(b0 + bb) * NS + s];
        s_m[bb][s]   = tmask[(b0 + bb) * NS + s];
    }
    for (int t = tx; t < BG * NR; t += 128) {
        int bb = t / NR, r = t % NR;
        s_rp[bb][r][0] = rpos[((b0 + bb) * NR + r) * 2 + 0];
        s_rp[bb][r][1] = rpos[((b0 + bb) * NR + r) * 2 + 1];
        s_rm[bb][r]    = rmask[(b0 + bb) * NR + r];
    }
    int f = blockIdx.x * 128 + tx;
    if (f < F) {
        for (int i = 0; i < NA; i++) s_fa[i][tx] = Fa_g[i * F + f];
    }
    __syncthreads();
    if (f >= F) return;

    float2 fc = Fc_g[f];
    float2 acc[BG];
#pragma unroll
    for (int bb = 0; bb < BG; bb++) acc[bb] = make_float2(0.f, 0.f);

    for (int s = 0; s < NS; s++) {
        float2 fp = Fp_g[s * F + f];
#pragma unroll
        for (int bb = 0; bb < BG; bb++) {
            int   a  = s_idx[bb][s];
            float mm = s_m[bb][s];
            float2 fa = s_fa[a][tx];
            acc[bb].x += mm * (fa.x * fp.x - fa.y * fp.y);
            acc[bb].y += mm * (fa.x * fp.y + fa.y * fp.x);
        }
    }
#pragma unroll
    for (int bb = 0; bb < BG; bb++) {
        for (int r = 0; r < NR; r++) {
            float2 f0 = Fp_g[s_rp[bb][r][0] * F + f];
            float2 f1 = Fp_g[s_rp[bb][r][1] * F + f];
            float2 t  = cmulf(cmulf(f0, f1), fc);
            float mm  = s_rm[bb][r];
            acc[bb].x += mm * t.x;
            acc[bb].y += mm * t.y;
        }
    }
#pragma unroll
    for (int bb = 0; bb < BG; bb++)
        Freq_g[(b0 + bb) * F + f] = acc[bb];
}

// ---------------- inverse FFT (Hermitian reconstruct + conj trick) -----
__global__ void __launch_bounds__(FFTTHREADS)
inv_fft_kernel() {
    extern __shared__ float2 sb[];
    int b = blockIdx.x;
    const float2* in = Freq_g + b * F;
    for (int i = threadIdx.x; i < D; i += blockDim.x) {
        float2 z;
        if (i < F) { z = in[i]; z.y = -z.y; }
        else       { z = in[D - i]; }
        sb[SK(i)] = z;
    }
    __syncthreads();
    fft_core(sb, sb + SBUF);
    const float inv = 1.0f / (float)D;
    for (int i = threadIdx.x; i < D; i += blockDim.x)
        Mol_g[b * D + i] = sb[SK(i)].x * inv;
}

// ---------------- projection ----------------
__global__ void init_out_kernel(const float* __restrict__ bias,
                                float* __restrict__ out) {
    int b = blockIdx.x, p = threadIdx.x;
    out[b * NP + p] = bias[p];
}

__global__ void __launch_bounds__(256)
proj_kernel(const float* __restrict__ Wm, float* __restrict__ out) {
    // grid (NP/64 = 4, DSPLIT = 125); block 256 = 16 p-groups x 16 b-groups
    __shared__ float sA[64][DLEN + 1];   // Mol tile  [b][dd]
    __shared__ float sW[64][DLEN + 1];   // W   tile  [p][dd]
    int pb = blockIdx.x;
    int ds = blockIdx.y;
    int dbase = ds * DLEN;
    int tid = threadIdx.x;

    for (int t = tid; t < 64 * DLEN; t += 256) {
        int r = t / DLEN, dd = t - r * DLEN;
        sA[r][dd] = Mol_g[r * D + dbase + dd];
    }
    for (int t = tid; t < 64 * DLEN; t += 256) {
        int r = t / DLEN, dd = t - r * DLEN;
        sW[r][dd] = Wm[(pb * 64 + r) * D + dbase + dd];
    }
    __syncthreads();

    int tx = tid & 15;        // p group (4 p each)
    int ty = tid >> 4;        // b group (4 b each)
    float acc[4][4];
#pragma unroll
    for (int i = 0; i < 4; i++)
#pragma unroll
        for (int j = 0; j < 4; j++) acc[i][j] = 0.f;

#pragma unroll 4
    for (int dd = 0; dd < DLEN; dd++) {
        float a0 = sA[ty * 4 + 0][dd];
        float a1 = sA[ty * 4 + 1][dd];
        float a2 = sA[ty * 4 + 2][dd];
        float a3 = sA[ty * 4 + 3][dd];
        float w0 = sW[tx * 4 + 0][dd];
        float w1 = sW[tx * 4 + 1][dd];
        float w2 = sW[tx * 4 + 2][dd];
        float w3 = sW[tx * 4 + 3][dd];
        acc[0][0] += a0 * w0; acc[0][1] += a0 * w1; acc[0][2] += a0 * w2; acc[0][3] += a0 * w3;
        acc[1][0] += a1 * w0; acc[1][1] += a1 * w1; acc[1][2] += a1 * w2; acc[1][3] += a1 * w3;
        acc[2][0] += a2 * w0; acc[2][1] += a2 * w1; acc[2][2] += a2 * w2; acc[2][3] += a2 * w3;
        acc[3][0] += a3 * w0; acc[3][1] += a3 * w1; acc[3][2] += a3 * w2; acc[3][3] += a3 * w3;
    }
#pragma unroll
    for (int i = 0; i < 4; i++) {
        int b = ty * 4 + i;
#pragma unroll
        for (int j = 0; j < 4; j++) {
            int p = pb * 64 + tx * 4 + j;
            atomicAdd(&out[b * NP + p], acc[i][j]);
        }
    }
}

// ---------------- launch ----------------
extern "C" void kernel_launch(void* const* d_in, const int* in_sizes, int n_in,
                              void* d_out, int out_size) {
    const float* atom  = (const float*)d_in[0];
    const float* pos   = (const float*)d_in[1];
    const float* clos  = (const float*)d_in[2];
    const float* Wm    = (const float*)d_in[3];
    const float* bias  = (const float*)d_in[4];
    const float* tmask = (const float*)d_in[5];
    const float* rmask = (const float*)d_in[6];
    const int*   aidx  = (const int*)d_in[7];
    const int*   rpos  = (const int*)d_in[8];
    float* out = (float*)d_out;

    size_t smem = 2 * (size_t)SBUF * sizeof(float2);   // 169984 B
    cudaFuncSetAttribute(fwd_fft_kernel,
                         cudaFuncAttributeMaxDynamicSharedMemorySize, (int)smem);
    cudaFuncSetAttribute(inv_fft_kernel,
                         cudaFuncAttributeMaxDynamicSharedMemorySize, (int)smem);

    build_T_kernel<<<(10000 + 255) / 256, 256>>>();
    fwd_fft_kernel<<<NA + NS + 1, FFTTHREADS, smem>>>(atom, pos, clos);

    dim3 cg((F + 127) / 128, NB / BG);
    combine_kernel<<<cg, 128>>>(tmask, rmask, aidx, rpos);

    inv_fft_kernel<<<NB, FFTTHREADS, smem>>>();

    init_out_kernel<<<NB, NP>>>(bias, out);
    dim3 pg(NP / 64, DSPLIT);
    proj_kernel<<<pg, 256>>>(Wm, out);
}